// round 16
// baseline (speedup 1.0000x reference)
#include <cuda_runtime.h>
#include <math.h>

#define S 618
#define B 16
#define EPS 1e-6f

typedef unsigned long long u64;

// scratch: normalized q and k multivectors, [side][b*S + n][8]
__device__ float g_qk[2][B * S * 8];
// split-K partials: [side][slice][b*S + n][8]
#define SPLITK 20
__device__ float g_part[2][SPLITK][B * S * 8];

// ---------------------------------------------------------------------------
// f32x2 helpers
// ---------------------------------------------------------------------------
__device__ __forceinline__ u64 pk2(float lo, float hi) {
    u64 r; asm("mov.b64 %0, {%1, %2};" : "=l"(r) : "f"(lo), "f"(hi)); return r;
}
__device__ __forceinline__ u64 mul2(u64 a, u64 b) {
    u64 d; asm("mul.rn.f32x2 %0, %1, %2;" : "=l"(d) : "l"(a), "l"(b)); return d;
}
__device__ __forceinline__ u64 fma2(u64 a, u64 b, u64 c) {
    u64 d; asm("fma.rn.f32x2 %0, %1, %2, %3;" : "=l"(d) : "l"(a), "l"(b), "l"(c)); return d;
}
__device__ __forceinline__ void up2(u64 v, float& lo, float& hi) {
    asm("mov.b64 {%0, %1}, %2;" : "=f"(lo), "=f"(hi) : "l"(v));
}

// ---------------------------------------------------------------------------
// cp.async helpers
// ---------------------------------------------------------------------------
__device__ __forceinline__ void cp_async16(void* smem_dst, const void* gsrc, bool pred) {
    unsigned saddr = (unsigned)__cvta_generic_to_shared(smem_dst);
    int sz = pred ? 16 : 0;   // sz=0 -> zero-fill 16B
    asm volatile("cp.async.ca.shared.global [%0], [%1], 16, %2;\n"
                 :: "r"(saddr), "l"(gsrc), "r"(sz));
}
__device__ __forceinline__ void cp_commit() {
    asm volatile("cp.async.commit_group;\n");
}

// ---------------------------------------------------------------------------
// Kernel A1: partial mv_linear, splitK = 20, register tile 2b x 2n (32 acc).
// Block 128 = 8 bt x 16 nt; thread owns batches (bt, bt+8) and n (n0+nt,
// n0+16+nt). grid = (20 n-tiles(32), 20 m-slices, 2 sides) = 800 blocks.
// Slice s processes chunks c = s*2 + j (j = 0..1); chunks 0..38 real,
// chunk 39 zero-filled by predication. launch_bounds(128, 5) targets
// ~100 regs so 5 blocks (20 warps) fit per SM instead of 4.
// ---------------------------------------------------------------------------
constexpr int MCQ = 16;   // m per chunk
constexpr int NCH = 2;    // chunks per slice
constexpr int TNB = 32;   // n per block

__global__ __launch_bounds__(128, 5) void qk_partial_kernel(
    const float* __restrict__ x,
    const float* __restrict__ qw,
    const float* __restrict__ kw)
{
    const int side  = blockIdx.z;
    const int slice = blockIdx.y;
    const float* __restrict__ w = side ? kw : qw;

    const int n0  = blockIdx.x * TNB;
    const int tid = threadIdx.x;
    const int nt  = tid & 15;         // local n within 16
    const int bt  = tid >> 4;         // batch 0..7 (owns bt and bt+8)
    const int na  = n0 + nt;
    const int nb  = n0 + 16 + nt;

    __shared__ float4 sw[2][TNB][MCQ + 1];
    __shared__ float  sx[2][B][MCQ * 8 + 4];

    float aA0[8] = {0,0,0,0,0,0,0,0}, aA1[8] = {0,0,0,0,0,0,0,0};
    float aB0[8] = {0,0,0,0,0,0,0,0}, aB1[8] = {0,0,0,0,0,0,0,0};

    auto prefetch = [&](int j) {
        const int mb  = (slice * NCH + j) * MCQ;
        const int buf = j & 1;
        #pragma unroll
        for (int r = 0; r < 4; r++) {   // w: 32n x 16m float4 = 512, 4/thread
            int idx = tid + r * 128;
            int wn = idx >> 4;
            int wm = idx & 15;
            int gn = n0 + wn;
            int gm = mb + wm;
            bool p = (gn < S) && (gm < S);
            const float* src = w + (p ? ((size_t)gn * S + gm) * 4 : 0);
            cp_async16(&sw[buf][wn][wm], src, p);
        }
        #pragma unroll
        for (int r = 0; r < 4; r++) {   // x: 512 float4, 4/thread
            int idx  = tid + r * 128;
            int xb   = idx >> 5;
            int off  = idx & 31;
            int mm   = off >> 1;
            int half = (off & 1) * 4;
            int gm   = mb + mm;
            bool p = (gm < S);
            const float* src = x + (p ? ((size_t)xb * S + gm) * 8 + half : 0);
            cp_async16(&sx[buf][xb][mm * 8 + half], src, p);
        }
        cp_commit();
    };

    prefetch(0);

    #pragma unroll 1
    for (int j = 0; j < NCH; j++) {
        if (j + 1 < NCH) {
            prefetch(j + 1);
            asm volatile("cp.async.wait_group 1;\n");
        } else {
            asm volatile("cp.async.wait_group 0;\n");
        }
        __syncthreads();

        const int buf = j & 1;
        #pragma unroll
        for (int mm = 0; mm < MCQ; mm++) {
            float4 wa = sw[buf][nt][mm];
            float4 wb = sw[buf][nt + 16][mm];
            float4 x0 = *reinterpret_cast<const float4*>(&sx[buf][bt][mm * 8]);
            float4 x1 = *reinterpret_cast<const float4*>(&sx[buf][bt][mm * 8 + 4]);
            float4 y0 = *reinterpret_cast<const float4*>(&sx[buf][bt + 8][mm * 8]);
            float4 y1 = *reinterpret_cast<const float4*>(&sx[buf][bt + 8][mm * 8 + 4]);

            aA0[0] += x0.x * wa.x;  aA0[1] += x0.y * wa.y;
            aA0[2] += x0.z * wa.y;  aA0[3] += x0.w * wa.y;
            aA0[4] += x1.x * wa.z;  aA0[5] += x1.y * wa.z;
            aA0[6] += x1.z * wa.z;  aA0[7] += x1.w * wa.w;

            aA1[0] += y0.x * wa.x;  aA1[1] += y0.y * wa.y;
            aA1[2] += y0.z * wa.y;  aA1[3] += y0.w * wa.y;
            aA1[4] += y1.x * wa.z;  aA1[5] += y1.y * wa.z;
            aA1[6] += y1.z * wa.z;  aA1[7] += y1.w * wa.w;

            aB0[0] += x0.x * wb.x;  aB0[1] += x0.y * wb.y;
            aB0[2] += x0.z * wb.y;  aB0[3] += x0.w * wb.y;
            aB0[4] += x1.x * wb.z;  aB0[5] += x1.y * wb.z;
            aB0[6] += x1.z * wb.z;  aB0[7] += x1.w * wb.w;

            aB1[0] += y0.x * wb.x;  aB1[1] += y0.y * wb.y;
            aB1[2] += y0.z * wb.y;  aB1[3] += y0.w * wb.y;
            aB1[4] += y1.x * wb.z;  aB1[5] += y1.y * wb.z;
            aB1[6] += y1.z * wb.z;  aB1[7] += y1.w * wb.w;
        }
        __syncthreads();
    }

    float* base = &g_part[side][slice][0];
    if (na < S) {
        float* o0 = base + ((size_t)bt * S + na) * 8;
        *reinterpret_cast<float4*>(o0)     = make_float4(aA0[0], aA0[1], aA0[2], aA0[3]);
        *reinterpret_cast<float4*>(o0 + 4) = make_float4(aA0[4], aA0[5], aA0[6], aA0[7]);
        float* o1 = base + ((size_t)(bt + 8) * S + na) * 8;
        *reinterpret_cast<float4*>(o1)     = make_float4(aA1[0], aA1[1], aA1[2], aA1[3]);
        *reinterpret_cast<float4*>(o1 + 4) = make_float4(aA1[4], aA1[5], aA1[6], aA1[7]);
    }
    if (nb < S) {
        float* o0 = base + ((size_t)bt * S + nb) * 8;
        *reinterpret_cast<float4*>(o0)     = make_float4(aB0[0], aB0[1], aB0[2], aB0[3]);
        *reinterpret_cast<float4*>(o0 + 4) = make_float4(aB0[4], aB0[5], aB0[6], aB0[7]);
        float* o1 = base + ((size_t)(bt + 8) * S + nb) * 8;
        *reinterpret_cast<float4*>(o1)     = make_float4(aB1[0], aB1[1], aB1[2], aB1[3]);
        *reinterpret_cast<float4*>(o1 + 4) = make_float4(aB1[4], aB1[5], aB1[6], aB1[7]);
    }
}

// ---------------------------------------------------------------------------
// Kernel A2: reduce SPLITK partials + bias + grade-norm normalize -> g_qk.
// ---------------------------------------------------------------------------
__global__ __launch_bounds__(256) void qk_finalize_kernel(
    const float* __restrict__ qb, const float* __restrict__ kb,
    const float* __restrict__ a)
{
    int gid = blockIdx.x * 256 + threadIdx.x;
    const int total = 2 * B * S;
    if (gid >= total) return;
    const int n    = gid % S;
    const int b    = (gid / S) % B;
    const int side = gid / (S * B);
    const float* __restrict__ bias = side ? kb : qb;

    const size_t off = ((size_t)b * S + n) * 8;
    float r0 = 0.f, r1 = 0.f, r2 = 0.f, r3 = 0.f;
    float r4 = 0.f, r5 = 0.f, r6 = 0.f, r7 = 0.f;
    #pragma unroll
    for (int p = 0; p < SPLITK; p++) {
        const float* src = &g_part[side][p][off];
        float4 v0 = *reinterpret_cast<const float4*>(src);
        float4 v1 = *reinterpret_cast<const float4*>(src + 4);
        r0 += v0.x; r1 += v0.y; r2 += v0.z; r3 += v0.w;
        r4 += v1.x; r5 += v1.y; r6 += v1.z; r7 += v1.w;
    }
    r0 += bias[n];

    float nm0 = fabsf(r0);
    float nm1 = sqrtf(r1 * r1 + r2 * r2 + r3 * r3);
    float nm2 = sqrtf(r4 * r4 + r5 * r5 + r6 * r6);
    float nm3 = fabsf(r7);

    const float* ap = a + (size_t)n * 4;
    float s0 = 1.f / (1.f + expf(-ap[0]));
    float s1 = 1.f / (1.f + expf(-ap[1]));
    float s2 = 1.f / (1.f + expf(-ap[2]));
    float s3 = 1.f / (1.f + expf(-ap[3]));

    float d0 = 1.f / (s0 * (nm0 - 1.f) + 1.f + EPS);
    float d1 = 1.f / (s1 * (nm1 - 1.f) + 1.f + EPS);
    float d2 = 1.f / (s2 * (nm2 - 1.f) + 1.f + EPS);
    float d3 = 1.f / (s3 * (nm3 - 1.f) + 1.f + EPS);

    float* o = &g_qk[side][off];
    *reinterpret_cast<float4*>(o)     = make_float4(r0 * d0, r1 * d1, r2 * d1, r3 * d1);
    *reinterpret_cast<float4*>(o + 4) = make_float4(r4 * d2, r5 * d2, r6 * d2, r7 * d3);
}

// ---------------------------------------------------------------------------
// Kernel B: pairwise geometric product, uniform-FMA + f32x2 over m-pairs.
// (R15 configuration -- at the L2 store-bandwidth wall, do not touch)
// ---------------------------------------------------------------------------
#define NHALF 320

__device__ __forceinline__ void stcs4(float* p, float4 v) {
    asm volatile("st.global.cs.v4.f32 [%0], {%1, %2, %3, %4};"
                 :: "l"(p), "f"(v.x), "f"(v.y), "f"(v.z), "f"(v.w) : "memory");
}

__global__ __launch_bounds__(128) void gp_kernel(float* __restrict__ out)
{
    const int b  = blockIdx.z;
    const int h  = blockIdx.y;
    const int m0 = blockIdx.x * 8;
    const int nstart = h * NHALF;
    const int ncount = h ? (S - NHALF) : NHALF;   // 298 or 320
    const int tid  = threadIdx.x;
    const int lane = tid & 31;
    const int w    = tid >> 5;

    // layout: [e_lo NHALF][pad 4][o_lo NHALF][pad 4][e_hi NHALF][pad 4][o_hi NHALF]
    __shared__ float4 skbuf[4 * NHALF + 12];
    __shared__ float4 sq[8][2];

    float4* const e_lo = skbuf;
    float4* const o_lo = skbuf + NHALF + 4;        // +64B -> bank shift 16
    float4* const e_hi = skbuf + 2 * NHALF + 8;
    float4* const o_hi = skbuf + 3 * NHALF + 12;

    // stage this block's n-half of k[b]: both variants
    const float* kbase = &g_qk[1][((size_t)b * S + nstart) * 8];
    for (int r = tid; r < NHALF; r += 128) {
        float4 kl = make_float4(0.f, 0.f, 0.f, 0.f), kh = kl;
        if (r < ncount) {
            kl = *reinterpret_cast<const float4*>(kbase + (size_t)r * 8);
            kh = *reinterpret_cast<const float4*>(kbase + (size_t)r * 8 + 4);
        }
        e_lo[r] = kl;
        e_hi[r] = kh;
        // k' = k*(-e123) = (k7, k6, -k5, k4, -k3, k2, -k1, -k0)
        o_lo[r] = make_float4( kh.w,  kh.z, -kh.y,  kh.x);
        o_hi[r] = make_float4(-kl.w,  kl.z, -kl.y, -kl.x);
    }
    // stage q rows m0..m0+7
    if (tid < 16) {
        int r = tid >> 1, half = tid & 1;
        int row = m0 + r;
        float4 v = make_float4(0.f, 0.f, 0.f, 0.f);
        if (row < S)
            v = *reinterpret_cast<const float4*>(&g_qk[0][((size_t)b * S + row) * 8 + half * 4]);
        sq[r][half] = v;
    }
    __syncthreads();

    const int m = m0 + 2 * w;
    if (m >= S) return;
    const bool has2 = (m + 1 < S);

    // pack q pairs (m in lo, m+1 in hi); row m+1 staged as zeros if OOB
    float4 qlA = sq[2 * w][0],     qhA = sq[2 * w][1];
    float4 qlB = sq[2 * w + 1][0], qhB = sq[2 * w + 1][1];
    u64 qp0 = pk2(qlA.x, qlB.x);
    u64 qp1 = pk2(qlA.y, qlB.y);
    u64 qp2 = pk2(qlA.z, qlB.z), qn2 = pk2(-qlA.z, -qlB.z);
    u64 qp3 = pk2(qlA.w, qlB.w), qn3 = pk2(-qlA.w, -qlB.w);
    u64 qp4 = pk2(qhA.x, qhB.x), qn4 = pk2(-qhA.x, -qhB.x);
    u64 qp5 = pk2(qhA.y, qhB.y), qn5 = pk2(-qhA.y, -qhB.y);
    u64 qp6 = pk2(qhA.z, qhB.z), qn6 = pk2(-qhA.z, -qhB.z);
    u64 qp7 = pk2(qhA.w, qhB.w), qn7 = pk2(-qhA.w, -qhB.w);

    const int  jhalf = lane & 1;
    const int  nlane = lane >> 1;
    const float4* __restrict__ klp = jhalf ? o_lo : e_lo;
    const float4* __restrict__ khp = jhalf ? o_hi : e_hi;

    float* const rowA = out + (((size_t)b * S + m) * S + nstart) * 8 + jhalf * 4;
    float* const rowB = rowA + (size_t)S * 8;

    auto body = [&](int n) {   // n = local index within the half
        float4 kl = klp[n];
        float4 kh = khp[n];
        u64 kd, o0, o1, o2, o3;
        kd = pk2(kl.x, kl.x);   // k0
        o0 = mul2(qp0, kd); o1 = mul2(qp1, kd); o2 = mul2(qp2, kd); o3 = mul2(qp3, kd);
        kd = pk2(kl.y, kl.y);   // k1
        o0 = fma2(qp1, kd, o0); o1 = fma2(qp0, kd, o1); o2 = fma2(qn4, kd, o2); o3 = fma2(qn5, kd, o3);
        kd = pk2(kl.z, kl.z);   // k2
        o0 = fma2(qp2, kd, o0); o1 = fma2(qp4, kd, o1); o2 = fma2(qp0, kd, o2); o3 = fma2(qn6, kd, o3);
        kd = pk2(kl.w, kl.w);   // k3
        o0 = fma2(qp3, kd, o0); o1 = fma2(qp5, kd, o1); o2 = fma2(qp6, kd, o2); o3 = fma2(qp0, kd, o3);
        kd = pk2(kh.x, kh.x);   // k4
        o0 = fma2(qn4, kd, o0); o1 = fma2(qn2, kd, o1); o2 = fma2(qp1, kd, o2); o3 = fma2(qn7, kd, o3);
        kd = pk2(kh.y, kh.y);   // k5
        o0 = fma2(qn5, kd, o0); o1 = fma2(qn3, kd, o1); o2 = fma2(qp7, kd, o2); o3 = fma2(qp1, kd, o3);
        kd = pk2(kh.z, kh.z);   // k6
        o0 = fma2(qn6, kd, o0); o1 = fma2(qn7, kd, o1); o2 = fma2(qn3, kd, o2); o3 = fma2(qp2, kd, o3);
        kd = pk2(kh.w, kh.w);   // k7
        o0 = fma2(qn7, kd, o0); o1 = fma2(qn6, kd, o1); o2 = fma2(qp5, kd, o2); o3 = fma2(qn4, kd, o3);

        float a0, b0, a1, b1, a2, b2, a3, b3;
        up2(o0, a0, b0); up2(o1, a1, b1); up2(o2, a2, b2); up2(o3, a3, b3);

        // even lanes: (o0..o3); odd lanes: results (o7,o6,-o5,o4) -> (o4..o7)=(r3,-r2,r1,r0)
        float4 vA = jhalf ? make_float4(a3, -a2, a1, a0) : make_float4(a0, a1, a2, a3);
        float4 vB = jhalf ? make_float4(b3, -b2, b1, b0) : make_float4(b0, b1, b2, b3);

        stcs4(rowA + (size_t)n * 8, vA);
        if (has2)
            stcs4(rowB + (size_t)n * 8, vB);
    };

    const int nfull = ncount >> 4;          // 20 (h=0) or 18 (h=1)
    #pragma unroll 2
    for (int j = 0; j < nfull; j++)
        body(j * 16 + nlane);
    {   // tail (h=1 only): local n = 288 + nlane, valid while < ncount
        const int n = nfull * 16 + nlane;
        if (n < ncount) body(n);
    }
}

// ---------------------------------------------------------------------------
extern "C" void kernel_launch(void* const* d_in, const int* in_sizes, int n_in,
                              void* d_out, int out_size)
{
    const float* x  = (const float*)d_in[0];
    const float* qw = (const float*)d_in[1];
    const float* qb = (const float*)d_in[2];
    const float* kw = (const float*)d_in[3];
    const float* kb = (const float*)d_in[4];
    const float* a  = (const float*)d_in[5];
    float* out = (float*)d_out;

    dim3 gridA1((S + TNB - 1) / TNB, SPLITK, 2);
    qk_partial_kernel<<<gridA1, 128>>>(x, qw, kw);

    int totalA2 = 2 * B * S;
    qk_finalize_kernel<<<(totalA2 + 255) / 256, 256>>>(qb, kb, a);

    dim3 gridB((S + 7) / 8, 2, B);
    gp_kernel<<<gridB, 128>>>(out);
}

// round 17
// speedup vs baseline: 1.0367x; 1.0367x over previous
#include <cuda_runtime.h>
#include <math.h>

#define S 618
#define B 16
#define EPS 1e-6f

typedef unsigned long long u64;

// scratch: normalized q and k multivectors, [side][b*S + n][8]
__device__ float g_qk[2][B * S * 8];
// split-K partials: [side][slice][b*S + n][8]
#define SPLITK 13
__device__ float g_part[2][SPLITK][B * S * 8];

// ---------------------------------------------------------------------------
// f32x2 helpers
// ---------------------------------------------------------------------------
__device__ __forceinline__ u64 pk2(float lo, float hi) {
    u64 r; asm("mov.b64 %0, {%1, %2};" : "=l"(r) : "f"(lo), "f"(hi)); return r;
}
__device__ __forceinline__ u64 mul2(u64 a, u64 b) {
    u64 d; asm("mul.rn.f32x2 %0, %1, %2;" : "=l"(d) : "l"(a), "l"(b)); return d;
}
__device__ __forceinline__ u64 fma2(u64 a, u64 b, u64 c) {
    u64 d; asm("fma.rn.f32x2 %0, %1, %2, %3;" : "=l"(d) : "l"(a), "l"(b), "l"(c)); return d;
}
__device__ __forceinline__ void up2(u64 v, float& lo, float& hi) {
    asm("mov.b64 {%0, %1}, %2;" : "=f"(lo), "=f"(hi) : "l"(v));
}

// ---------------------------------------------------------------------------
// cp.async helpers
// ---------------------------------------------------------------------------
__device__ __forceinline__ void cp_async16(void* smem_dst, const void* gsrc, bool pred) {
    unsigned saddr = (unsigned)__cvta_generic_to_shared(smem_dst);
    int sz = pred ? 16 : 0;   // sz=0 -> zero-fill 16B
    asm volatile("cp.async.ca.shared.global [%0], [%1], 16, %2;\n"
                 :: "r"(saddr), "l"(gsrc), "r"(sz));
}
__device__ __forceinline__ void cp_commit() {
    asm volatile("cp.async.commit_group;\n");
}

// ---------------------------------------------------------------------------
// Kernel A1: partial mv_linear, splitK = 13, register tile 2b x 2n (32 acc).
// Block 128 = 8 bt x 16 nt; thread owns batches (bt, bt+8) and n (n0+nt,
// n0+16+nt). grid = (20 n-tiles(32), 13 m-slices, 2 sides) = 520 blocks.
// Slice s processes chunks c = s*3 + j (j = 0..2) -> 39 chunks, exact cover.
// (Best measured configuration across R10-R16 ablations.)
// ---------------------------------------------------------------------------
constexpr int MCQ = 16;   // m per chunk
constexpr int NCH = 3;    // chunks per slice
constexpr int TNB = 32;   // n per block

__global__ __launch_bounds__(128) void qk_partial_kernel(
    const float* __restrict__ x,
    const float* __restrict__ qw,
    const float* __restrict__ kw)
{
    const int side  = blockIdx.z;
    const int slice = blockIdx.y;
    const float* __restrict__ w = side ? kw : qw;

    const int n0  = blockIdx.x * TNB;
    const int tid = threadIdx.x;
    const int nt  = tid & 15;         // local n within 16
    const int bt  = tid >> 4;         // batch 0..7 (owns bt and bt+8)
    const int na  = n0 + nt;
    const int nb  = n0 + 16 + nt;

    __shared__ float4 sw[2][TNB][MCQ + 1];
    __shared__ float  sx[2][B][MCQ * 8 + 4];

    float aA0[8] = {0,0,0,0,0,0,0,0}, aA1[8] = {0,0,0,0,0,0,0,0};
    float aB0[8] = {0,0,0,0,0,0,0,0}, aB1[8] = {0,0,0,0,0,0,0,0};

    auto prefetch = [&](int j) {
        const int mb  = (slice * NCH + j) * MCQ;
        const int buf = j & 1;
        #pragma unroll
        for (int r = 0; r < 4; r++) {   // w: 32n x 16m float4 = 512, 4/thread
            int idx = tid + r * 128;
            int wn = idx >> 4;
            int wm = idx & 15;
            int gn = n0 + wn;
            int gm = mb + wm;
            bool p = (gn < S) && (gm < S);
            const float* src = w + (p ? ((size_t)gn * S + gm) * 4 : 0);
            cp_async16(&sw[buf][wn][wm], src, p);
        }
        #pragma unroll
        for (int r = 0; r < 4; r++) {   // x: 512 float4, 4/thread
            int idx  = tid + r * 128;
            int xb   = idx >> 5;
            int off  = idx & 31;
            int mm   = off >> 1;
            int half = (off & 1) * 4;
            int gm   = mb + mm;
            bool p = (gm < S);
            const float* src = x + (p ? ((size_t)xb * S + gm) * 8 + half : 0);
            cp_async16(&sx[buf][xb][mm * 8 + half], src, p);
        }
        cp_commit();
    };

    prefetch(0);

    #pragma unroll 1
    for (int j = 0; j < NCH; j++) {
        if (j + 1 < NCH) {
            prefetch(j + 1);
            asm volatile("cp.async.wait_group 1;\n");
        } else {
            asm volatile("cp.async.wait_group 0;\n");
        }
        __syncthreads();

        const int buf = j & 1;
        #pragma unroll
        for (int mm = 0; mm < MCQ; mm++) {
            float4 wa = sw[buf][nt][mm];
            float4 wb = sw[buf][nt + 16][mm];
            float4 x0 = *reinterpret_cast<const float4*>(&sx[buf][bt][mm * 8]);
            float4 x1 = *reinterpret_cast<const float4*>(&sx[buf][bt][mm * 8 + 4]);
            float4 y0 = *reinterpret_cast<const float4*>(&sx[buf][bt + 8][mm * 8]);
            float4 y1 = *reinterpret_cast<const float4*>(&sx[buf][bt + 8][mm * 8 + 4]);

            aA0[0] += x0.x * wa.x;  aA0[1] += x0.y * wa.y;
            aA0[2] += x0.z * wa.y;  aA0[3] += x0.w * wa.y;
            aA0[4] += x1.x * wa.z;  aA0[5] += x1.y * wa.z;
            aA0[6] += x1.z * wa.z;  aA0[7] += x1.w * wa.w;

            aA1[0] += y0.x * wa.x;  aA1[1] += y0.y * wa.y;
            aA1[2] += y0.z * wa.y;  aA1[3] += y0.w * wa.y;
            aA1[4] += y1.x * wa.z;  aA1[5] += y1.y * wa.z;
            aA1[6] += y1.z * wa.z;  aA1[7] += y1.w * wa.w;

            aB0[0] += x0.x * wb.x;  aB0[1] += x0.y * wb.y;
            aB0[2] += x0.z * wb.y;  aB0[3] += x0.w * wb.y;
            aB0[4] += x1.x * wb.z;  aB0[5] += x1.y * wb.z;
            aB0[6] += x1.z * wb.z;  aB0[7] += x1.w * wb.w;

            aB1[0] += y0.x * wb.x;  aB1[1] += y0.y * wb.y;
            aB1[2] += y0.z * wb.y;  aB1[3] += y0.w * wb.y;
            aB1[4] += y1.x * wb.z;  aB1[5] += y1.y * wb.z;
            aB1[6] += y1.z * wb.z;  aB1[7] += y1.w * wb.w;
        }
        __syncthreads();
    }

    float* base = &g_part[side][slice][0];
    if (na < S) {
        float* o0 = base + ((size_t)bt * S + na) * 8;
        *reinterpret_cast<float4*>(o0)     = make_float4(aA0[0], aA0[1], aA0[2], aA0[3]);
        *reinterpret_cast<float4*>(o0 + 4) = make_float4(aA0[4], aA0[5], aA0[6], aA0[7]);
        float* o1 = base + ((size_t)(bt + 8) * S + na) * 8;
        *reinterpret_cast<float4*>(o1)     = make_float4(aA1[0], aA1[1], aA1[2], aA1[3]);
        *reinterpret_cast<float4*>(o1 + 4) = make_float4(aA1[4], aA1[5], aA1[6], aA1[7]);
    }
    if (nb < S) {
        float* o0 = base + ((size_t)bt * S + nb) * 8;
        *reinterpret_cast<float4*>(o0)     = make_float4(aB0[0], aB0[1], aB0[2], aB0[3]);
        *reinterpret_cast<float4*>(o0 + 4) = make_float4(aB0[4], aB0[5], aB0[6], aB0[7]);
        float* o1 = base + ((size_t)(bt + 8) * S + nb) * 8;
        *reinterpret_cast<float4*>(o1)     = make_float4(aB1[0], aB1[1], aB1[2], aB1[3]);
        *reinterpret_cast<float4*>(o1 + 4) = make_float4(aB1[4], aB1[5], aB1[6], aB1[7]);
    }
}

// ---------------------------------------------------------------------------
// Kernel A2: reduce SPLITK partials + bias + grade-norm normalize -> g_qk.
// ---------------------------------------------------------------------------
__global__ __launch_bounds__(256) void qk_finalize_kernel(
    const float* __restrict__ qb, const float* __restrict__ kb,
    const float* __restrict__ a)
{
    int gid = blockIdx.x * 256 + threadIdx.x;
    const int total = 2 * B * S;
    if (gid >= total) return;
    const int n    = gid % S;
    const int b    = (gid / S) % B;
    const int side = gid / (S * B);
    const float* __restrict__ bias = side ? kb : qb;

    const size_t off = ((size_t)b * S + n) * 8;
    float r0 = 0.f, r1 = 0.f, r2 = 0.f, r3 = 0.f;
    float r4 = 0.f, r5 = 0.f, r6 = 0.f, r7 = 0.f;
    #pragma unroll
    for (int p = 0; p < SPLITK; p++) {
        const float* src = &g_part[side][p][off];
        float4 v0 = *reinterpret_cast<const float4*>(src);
        float4 v1 = *reinterpret_cast<const float4*>(src + 4);
        r0 += v0.x; r1 += v0.y; r2 += v0.z; r3 += v0.w;
        r4 += v1.x; r5 += v1.y; r6 += v1.z; r7 += v1.w;
    }
    r0 += bias[n];

    float nm0 = fabsf(r0);
    float nm1 = sqrtf(r1 * r1 + r2 * r2 + r3 * r3);
    float nm2 = sqrtf(r4 * r4 + r5 * r5 + r6 * r6);
    float nm3 = fabsf(r7);

    const float* ap = a + (size_t)n * 4;
    float s0 = 1.f / (1.f + expf(-ap[0]));
    float s1 = 1.f / (1.f + expf(-ap[1]));
    float s2 = 1.f / (1.f + expf(-ap[2]));
    float s3 = 1.f / (1.f + expf(-ap[3]));

    float d0 = 1.f / (s0 * (nm0 - 1.f) + 1.f + EPS);
    float d1 = 1.f / (s1 * (nm1 - 1.f) + 1.f + EPS);
    float d2 = 1.f / (s2 * (nm2 - 1.f) + 1.f + EPS);
    float d3 = 1.f / (s3 * (nm3 - 1.f) + 1.f + EPS);

    float* o = &g_qk[side][off];
    *reinterpret_cast<float4*>(o)     = make_float4(r0 * d0, r1 * d1, r2 * d1, r3 * d1);
    *reinterpret_cast<float4*>(o + 4) = make_float4(r4 * d2, r5 * d2, r6 * d2, r7 * d3);
}

// ---------------------------------------------------------------------------
// Kernel B: pairwise geometric product, uniform-FMA + f32x2 over m-pairs.
// n split in half per block (smem ~21 KB), 256 threads / 16 m-rows.
// At the DRAM pure-write wall (~5.7 TB/s effective) -- best measured form.
// ---------------------------------------------------------------------------
#define NHALF 320

__device__ __forceinline__ void stcs4(float* p, float4 v) {
    asm volatile("st.global.cs.v4.f32 [%0], {%1, %2, %3, %4};"
                 :: "l"(p), "f"(v.x), "f"(v.y), "f"(v.z), "f"(v.w) : "memory");
}

__global__ __launch_bounds__(256) void gp_kernel(float* __restrict__ out)
{
    const int b  = blockIdx.z;
    const int h  = blockIdx.y;
    const int m0 = blockIdx.x * 16;
    const int nstart = h * NHALF;
    const int ncount = h ? (S - NHALF) : NHALF;   // 298 or 320
    const int tid  = threadIdx.x;
    const int lane = tid & 31;
    const int w    = tid >> 5;

    // layout: [e_lo NHALF][pad 4][o_lo NHALF][pad 4][e_hi NHALF][pad 4][o_hi NHALF]
    __shared__ float4 skbuf[4 * NHALF + 12];
    __shared__ float4 sq[16][2];

    float4* const e_lo = skbuf;
    float4* const o_lo = skbuf + NHALF + 4;        // +64B -> bank shift 16
    float4* const e_hi = skbuf + 2 * NHALF + 8;
    float4* const o_hi = skbuf + 3 * NHALF + 12;

    // stage this block's n-half of k[b]: both variants
    const float* kbase = &g_qk[1][((size_t)b * S + nstart) * 8];
    for (int r = tid; r < NHALF; r += 256) {
        float4 kl = make_float4(0.f, 0.f, 0.f, 0.f), kh = kl;
        if (r < ncount) {
            kl = *reinterpret_cast<const float4*>(kbase + (size_t)r * 8);
            kh = *reinterpret_cast<const float4*>(kbase + (size_t)r * 8 + 4);
        }
        e_lo[r] = kl;
        e_hi[r] = kh;
        // k' = k*(-e123) = (k7, k6, -k5, k4, -k3, k2, -k1, -k0)
        o_lo[r] = make_float4( kh.w,  kh.z, -kh.y,  kh.x);
        o_hi[r] = make_float4(-kl.w,  kl.z, -kl.y, -kl.x);
    }
    // stage q rows m0..m0+15
    if (tid < 32) {
        int r = tid >> 1, half = tid & 1;
        int row = m0 + r;
        float4 v = make_float4(0.f, 0.f, 0.f, 0.f);
        if (row < S)
            v = *reinterpret_cast<const float4*>(&g_qk[0][((size_t)b * S + row) * 8 + half * 4]);
        sq[r][half] = v;
    }
    __syncthreads();

    const int m = m0 + 2 * w;
    if (m >= S) return;
    const bool has2 = (m + 1 < S);

    // pack q pairs (m in lo, m+1 in hi); row m+1 staged as zeros if OOB
    float4 qlA = sq[2 * w][0],     qhA = sq[2 * w][1];
    float4 qlB = sq[2 * w + 1][0], qhB = sq[2 * w + 1][1];
    u64 qp0 = pk2(qlA.x, qlB.x);
    u64 qp1 = pk2(qlA.y, qlB.y);
    u64 qp2 = pk2(qlA.z, qlB.z), qn2 = pk2(-qlA.z, -qlB.z);
    u64 qp3 = pk2(qlA.w, qlB.w), qn3 = pk2(-qlA.w, -qlB.w);
    u64 qp4 = pk2(qhA.x, qhB.x), qn4 = pk2(-qhA.x, -qhB.x);
    u64 qp5 = pk2(qhA.y, qhB.y), qn5 = pk2(-qhA.y, -qhB.y);
    u64 qp6 = pk2(qhA.z, qhB.z), qn6 = pk2(-qhA.z, -qhB.z);
    u64 qp7 = pk2(qhA.w, qhB.w), qn7 = pk2(-qhA.w, -qhB.w);

    const int  jhalf = lane & 1;
    const int  nlane = lane >> 1;
    const float4* __restrict__ klp = jhalf ? o_lo : e_lo;
    const float4* __restrict__ khp = jhalf ? o_hi : e_hi;

    float* const rowA = out + (((size_t)b * S + m) * S + nstart) * 8 + jhalf * 4;
    float* const rowB = rowA + (size_t)S * 8;

    auto body = [&](int n) {   // n = local index within the half
        float4 kl = klp[n];
        float4 kh = khp[n];
        u64 kd, o0, o1, o2, o3;
        kd = pk2(kl.x, kl.x);   // k0
        o0 = mul2(qp0, kd); o1 = mul2(qp1, kd); o2 = mul2(qp2, kd); o3 = mul2(qp3, kd);
        kd = pk2(kl.y, kl.y);   // k1
        o0 = fma2(qp1, kd, o0); o1 = fma2(qp0, kd, o1); o2 = fma2(qn4, kd, o2); o3 = fma2(qn5, kd, o3);
        kd = pk2(kl.z, kl.z);   // k2
        o0 = fma2(qp2, kd, o0); o1 = fma2(qp4, kd, o1); o2 = fma2(qp0, kd, o2); o3 = fma2(qn6, kd, o3);
        kd = pk2(kl.w, kl.w);   // k3
        o0 = fma2(qp3, kd, o0); o1 = fma2(qp5, kd, o1); o2 = fma2(qp6, kd, o2); o3 = fma2(qp0, kd, o3);
        kd = pk2(kh.x, kh.x);   // k4
        o0 = fma2(qn4, kd, o0); o1 = fma2(qn2, kd, o1); o2 = fma2(qp1, kd, o2); o3 = fma2(qn7, kd, o3);
        kd = pk2(kh.y, kh.y);   // k5
        o0 = fma2(qn5, kd, o0); o1 = fma2(qn3, kd, o1); o2 = fma2(qp7, kd, o2); o3 = fma2(qp1, kd, o3);
        kd = pk2(kh.z, kh.z);   // k6
        o0 = fma2(qn6, kd, o0); o1 = fma2(qn7, kd, o1); o2 = fma2(qn3, kd, o2); o3 = fma2(qp2, kd, o3);
        kd = pk2(kh.w, kh.w);   // k7
        o0 = fma2(qn7, kd, o0); o1 = fma2(qn6, kd, o1); o2 = fma2(qp5, kd, o2); o3 = fma2(qn4, kd, o3);

        float a0, b0, a1, b1, a2, b2, a3, b3;
        up2(o0, a0, b0); up2(o1, a1, b1); up2(o2, a2, b2); up2(o3, a3, b3);

        // even lanes: (o0..o3); odd lanes: results (o7,o6,-o5,o4) -> (o4..o7)=(r3,-r2,r1,r0)
        float4 vA = jhalf ? make_float4(a3, -a2, a1, a0) : make_float4(a0, a1, a2, a3);
        float4 vB = jhalf ? make_float4(b3, -b2, b1, b0) : make_float4(b0, b1, b2, b3);

        stcs4(rowA + (size_t)n * 8, vA);
        if (has2)
            stcs4(rowB + (size_t)n * 8, vB);
    };

    const int nfull = ncount >> 4;          // 20 (h=0) or 18 (h=1)
    #pragma unroll 2
    for (int j = 0; j < nfull; j++)
        body(j * 16 + nlane);
    {   // tail (h=1 only): local n = 288 + nlane, valid while < ncount
        const int n = nfull * 16 + nlane;
        if (n < ncount) body(n);
    }
}

// ---------------------------------------------------------------------------
extern "C" void kernel_launch(void* const* d_in, const int* in_sizes, int n_in,
                              void* d_out, int out_size)
{
    const float* x  = (const float*)d_in[0];
    const float* qw = (const float*)d_in[1];
    const float* qb = (const float*)d_in[2];
    const float* kw = (const float*)d_in[3];
    const float* kb = (const float*)d_in[4];
    const float* a  = (const float*)d_in[5];
    float* out = (float*)d_out;

    dim3 gridA1((S + TNB - 1) / TNB, SPLITK, 2);
    qk_partial_kernel<<<gridA1, 128>>>(x, qw, kw);

    int totalA2 = 2 * B * S;
    qk_finalize_kernel<<<(totalA2 + 255) / 256, 256>>>(qb, kb, a);

    dim3 gridB((S + 15) / 16, 2, B);
    gp_kernel<<<gridB, 256>>>(out);
}